// round 4
// baseline (speedup 1.0000x reference)
#include <cuda_runtime.h>
#include <cuda_bf16.h>
#include <cstdint>

#define ROUNDS 64
#define HID 256
#define BATCH 65536
#define M_TILE 128
#define THREADS 512
#define NUM_CTAS (BATCH / M_TILE)

#define A_STRIDE 272            // 256 + 16 pad -> conflict-free LDS
#define W_STRIDE 272
#define A_BYTES (M_TILE * A_STRIDE)          // 34816
#define W_BYTES (HID * W_STRIDE)             // 69632
#define SMEM_TOTAL (A_BYTES + 2 * W_BYTES + ROUNDS * 8 * 4)  // 176128

// scratch (allocation-free rule: __device__ globals)
__device__ unsigned char g_Wq[ROUNDS * HID * HID];  // |W| in {0,1} as int8
__device__ uint32_t g_noise[ROUNDS * 8];            // packed noise bits

// ---------------- helpers ----------------
__device__ __forceinline__ uint32_t smem_u32(const void* p) {
    uint32_t a;
    asm("{ .reg .u64 t; cvta.to.shared.u64 t, %1; cvt.u32.u64 %0, t; }" : "=r"(a) : "l"(p));
    return a;
}
__device__ __forceinline__ void cp16(uint32_t dst, const void* src) {
    asm volatile("cp.async.cg.shared.global [%0], [%1], 16;" :: "r"(dst), "l"(src));
}
__device__ __forceinline__ void cp_commit() {
    asm volatile("cp.async.commit_group;" ::: "memory");
}
__device__ __forceinline__ void cp_wait0() {
    asm volatile("cp.async.wait_group 0;" ::: "memory");
}
// s8 IMMA: D(16x8,s32) += A(16x32,s8) * B(32x8,s8)
__device__ __forceinline__ void mma8(int* c, const uint32_t* a, uint32_t b0, uint32_t b1) {
    asm volatile(
        "mma.sync.aligned.m16n8k32.row.col.s32.s8.s8.s32 "
        "{%0,%1,%2,%3}, {%4,%5,%6,%7}, {%8,%9}, {%0,%1,%2,%3};"
        : "+r"(c[0]), "+r"(c[1]), "+r"(c[2]), "+r"(c[3])
        : "r"(a[0]), "r"(a[1]), "r"(a[2]), "r"(a[3]), "r"(b0), "r"(b1));
}

// ---------------- prep kernels ----------------
__global__ void prep_W(const float4* __restrict__ W, int n4) {
    int i = blockIdx.x * blockDim.x + threadIdx.x;
    if (i < n4) {
        float4 v = W[i];
        // mod-2 algebra: -1 == 1, so |w| in {0,1}
        uint32_t pk = (v.x != 0.f ? 1u : 0u) | (v.y != 0.f ? 0x100u : 0u)
                    | (v.z != 0.f ? 0x10000u : 0u) | (v.w != 0.f ? 0x1000000u : 0u);
        reinterpret_cast<uint32_t*>(g_Wq)[i] = pk;
    }
}
__global__ void prep_noise(const float* __restrict__ noise) {
    int i = blockIdx.x * blockDim.x + threadIdx.x;
    if (i < ROUNDS * 8) {
        const float* src = noise + i * 32;
        uint32_t w = 0;
        #pragma unroll
        for (int b = 0; b < 32; ++b) w |= (src[b] > 0.5f ? 1u : 0u) << b;
        g_noise[i] = w;
    }
}

// ---------------- main kernel ----------------
__device__ __forceinline__ void load_W_async(uint32_t wbuf, const unsigned char* __restrict__ src, int tid) {
    #pragma unroll
    for (int i = 0; i < 8; ++i) {
        int c = tid + i * THREADS;          // 0..4095 : 16B chunks
        int j = c >> 4;                     // W row (output index)
        int k = (c & 15) << 4;              // byte offset within row
        cp16(wbuf + (uint32_t)j * W_STRIDE + (uint32_t)k, src + (size_t)j * HID + k);
    }
    cp_commit();
}

__global__ void __launch_bounds__(THREADS, 1)
tenshash_main(const float* __restrict__ state, float* __restrict__ out) {
    extern __shared__ char smem[];
    char* A = smem;
    uint32_t sbase = smem_u32(smem);
    uint32_t Wbuf[2] = { sbase + A_BYTES, sbase + A_BYTES + W_BYTES };
    char* Wptr[2] = { smem + A_BYTES, smem + A_BYTES + W_BYTES };
    uint32_t* nsh = reinterpret_cast<uint32_t*>(smem + A_BYTES + 2 * W_BYTES);

    const int tid  = threadIdx.x;
    const int wid  = tid >> 5;
    const int lane = tid & 31;
    const int mgrp = wid & 3;      // rows mgrp*32 .. +31
    const int ngrp = wid >> 2;     // cols ngrp*64 .. +63
    const int qrow = lane >> 2;    // 0..7
    const int qcol = lane & 3;     // 0..3

    // kick off W round 0 while we init state + noise
    load_W_async(Wbuf[0], g_Wq, tid);

    for (int i = tid; i < ROUNDS * 8; i += THREADS) nsh[i] = g_noise[i];

    const int row0 = blockIdx.x * M_TILE;
    for (int i = tid; i < M_TILE * (HID / 4); i += THREADS) {
        int row = i >> 6;                  // 64 float4 per row
        int c4  = (i & 63);
        float4 v = reinterpret_cast<const float4*>(state + (size_t)(row0 + row) * HID)[c4];
        uint32_t pk = (v.x != 0.f ? 1u : 0u) | (v.y != 0.f ? 0x100u : 0u)
                    | (v.z != 0.f ? 0x10000u : 0u) | (v.w != 0.f ? 0x1000000u : 0u);
        *reinterpret_cast<uint32_t*>(A + row * A_STRIDE + c4 * 4) = pk;
    }
    cp_wait0();
    __syncthreads();

    // per-warp base addresses
    char* Arow = A + (mgrp * 32 + qrow) * A_STRIDE;   // m-tile row base (add mt*16*stride, +8*stride)

    int acc[2][8][4];

    for (int r = 0; r < ROUNDS; ++r) {
        // prefetch next round's W into the other buffer
        if (r + 1 < ROUNDS)
            load_W_async(Wbuf[(r + 1) & 1], g_Wq + (size_t)(r + 1) * (HID * HID), tid);

        #pragma unroll
        for (int mt = 0; mt < 2; ++mt)
            #pragma unroll
            for (int nt = 0; nt < 8; ++nt)
                #pragma unroll
                for (int i = 0; i < 4; ++i) acc[mt][nt][i] = 0;

        char* Wrow = Wptr[r & 1] + (ngrp * 64 + qrow) * W_STRIDE;

        #pragma unroll
        for (int ks = 0; ks < 8; ++ks) {
            uint32_t a[2][4];
            #pragma unroll
            for (int mt = 0; mt < 2; ++mt) {
                char* pa = Arow + mt * (16 * A_STRIDE) + ks * 32 + qcol * 4;
                // PTX m16n8k32 s8 A fragment order:
                // a0=(row g, k_lo), a1=(row g+8, k_lo), a2=(row g, k_hi), a3=(row g+8, k_hi)
                a[mt][0] = *reinterpret_cast<uint32_t*>(pa);
                a[mt][1] = *reinterpret_cast<uint32_t*>(pa + 8 * A_STRIDE);
                a[mt][2] = *reinterpret_cast<uint32_t*>(pa + 16);
                a[mt][3] = *reinterpret_cast<uint32_t*>(pa + 8 * A_STRIDE + 16);
            }
            #pragma unroll
            for (int nt = 0; nt < 8; ++nt) {
                char* pb = Wrow + nt * (8 * W_STRIDE) + ks * 32 + qcol * 4;
                uint32_t b0 = *reinterpret_cast<uint32_t*>(pb);
                uint32_t b1 = *reinterpret_cast<uint32_t*>(pb + 16);
                mma8(acc[0][nt], a[0], b0, b1);
                mma8(acc[1][nt], a[1], b0, b1);
            }
        }

        __syncthreads();   // all mma reads of A done CTA-wide

        // epilogue: bit = (acc & 1) ^ noise  -> back into A as int8
        #pragma unroll
        for (int mt = 0; mt < 2; ++mt) {
            #pragma unroll
            for (int nt = 0; nt < 8; ++nt) {
                int col = ngrp * 64 + nt * 8 + qcol * 2;
                uint32_t nw = nsh[r * 8 + (col >> 5)];
                uint32_t n0 = (nw >> (col & 31)) & 1u;
                uint32_t n1 = (nw >> ((col & 31) + 1)) & 1u;
                uint32_t b0 = ((uint32_t)acc[mt][nt][0] & 1u) ^ n0;
                uint32_t b1 = ((uint32_t)acc[mt][nt][1] & 1u) ^ n1;
                uint32_t b2 = ((uint32_t)acc[mt][nt][2] & 1u) ^ n0;
                uint32_t b3 = ((uint32_t)acc[mt][nt][3] & 1u) ^ n1;
                char* pd = Arow + mt * (16 * A_STRIDE) + col;
                *reinterpret_cast<uint16_t*>(pd)                = (uint16_t)(b0 | (b1 << 8));
                *reinterpret_cast<uint16_t*>(pd + 8 * A_STRIDE) = (uint16_t)(b2 | (b3 << 8));
            }
        }

        if (r + 1 < ROUNDS) cp_wait0();   // next W resident
        __syncthreads();                  // epilogue writes + W buffer visible
    }

    // write final state as fp32
    for (int i = tid; i < M_TILE * (HID / 4); i += THREADS) {
        int row = i >> 6;
        int c4  = (i & 63);
        uint32_t pk = *reinterpret_cast<uint32_t*>(A + row * A_STRIDE + c4 * 4);
        float4 v;
        v.x = (float)(pk & 0xffu);
        v.y = (float)((pk >> 8) & 0xffu);
        v.z = (float)((pk >> 16) & 0xffu);
        v.w = (float)((pk >> 24) & 0xffu);
        reinterpret_cast<float4*>(out + (size_t)(row0 + row) * HID)[c4] = v;
    }
}

// ---------------- launch ----------------
extern "C" void kernel_launch(void* const* d_in, const int* in_sizes, int n_in,
                              void* d_out, int out_size) {
    const float* state    = (const float*)d_in[0];   // [65536, 256]
    const float* matrices = (const float*)d_in[1];   // [64, 256, 256]
    const float* noise    = (const float*)d_in[2];   // [64, 256]
    float* out = (float*)d_out;

    int n4 = ROUNDS * HID * HID / 4;
    prep_W<<<(n4 + 511) / 512, 512>>>((const float4*)matrices, n4);
    prep_noise<<<2, 256>>>(noise);

    cudaFuncSetAttribute(tenshash_main, cudaFuncAttributeMaxDynamicSharedMemorySize, SMEM_TOTAL);
    tenshash_main<<<NUM_CTAS, THREADS, SMEM_TOTAL>>>(state, out);
}

// round 5
// speedup vs baseline: 7.9558x; 7.9558x over previous
#include <cuda_runtime.h>
#include <cuda_bf16.h>
#include <cstdint>

#define ROUNDS 64
#define HID 256
#define BATCH 65536
#define NBW (BATCH / 32)            // 2048 packed batch words
#define BWSET 32                    // bw words per CTA (one per lane)
#define JSPLIT 2
#define JCTA (HID / JSPLIT)         // 128 j per CTA
#define RK_THREADS 512              // 16 warps

// ---------------- device-global scratch (no allocs allowed) ----------------
__device__ uint32_t g_S[2][HID * NBW];          // bit-sliced state [k][bw], ping-pong (2x2MB)
__device__ uint32_t g_Wb[ROUNDS * HID * 8];     // W bits: [r][j][8 words over k]
__device__ uint32_t g_nm[ROUNDS * HID];         // noise masks: 0 or 0xFFFFFFFF

// ---------------- prep: pack |W| bits ----------------
__global__ void pack_W(const float* __restrict__ W) {
    int w = blockIdx.x * blockDim.x + threadIdx.x;      // word index
    if (w >= ROUNDS * HID * 8) return;
    const float* src = W + (size_t)w * 32;              // 32 consecutive k of row (r,j)
    uint32_t bits = 0;
    #pragma unroll
    for (int q = 0; q < 8; ++q) {
        float4 v = reinterpret_cast<const float4*>(src)[q];
        bits |= (v.x != 0.f ? 1u : 0u) << (q * 4 + 0);
        bits |= (v.y != 0.f ? 1u : 0u) << (q * 4 + 1);
        bits |= (v.z != 0.f ? 1u : 0u) << (q * 4 + 2);
        bits |= (v.w != 0.f ? 1u : 0u) << (q * 4 + 3);
    }
    g_Wb[w] = bits;
}

// ---------------- prep: noise -> full masks ----------------
__global__ void pack_noise(const float* __restrict__ noise) {
    int i = blockIdx.x * blockDim.x + threadIdx.x;
    if (i < ROUNDS * HID) g_nm[i] = (noise[i] != 0.f) ? 0xFFFFFFFFu : 0u;
}

// ---------------- prep: bit-slice the state ----------------
// S[k][bw]: bit b = state[bw*32+b][k]
__global__ void pack_state(const float* __restrict__ state) {
    int warp = (blockIdx.x * blockDim.x + threadIdx.x) >> 5;  // one warp per bw
    int lane = threadIdx.x & 31;
    if (warp >= NBW) return;
    const float* base = state + (size_t)warp * 32 * HID;
    #pragma unroll
    for (int kc = 0; kc < 8; ++kc) {
        int k = kc * 32 + lane;
        uint32_t word = 0;
        #pragma unroll
        for (int b = 0; b < 32; ++b)
            word |= (base[(size_t)b * HID + k] != 0.f ? 1u : 0u) << b;
        g_S[0][(size_t)k * NBW + warp] = word;
    }
}

// ---------------- per-round GF(2) kernel ----------------
// grid (64, 2): x = bw-set (32 words), y = j-half (128 j)
// SMEM: LUT[64 chunks][16 entries][32 lanes] (128KB) + wb slice (4KB)
#define LUT_WORDS (64 * 16 * 32)
#define RK_SMEM (LUT_WORDS * 4 + JCTA * 8 * 4)

__global__ void __launch_bounds__(RK_THREADS, 1)
round_gf2(const uint32_t* __restrict__ Sin, uint32_t* __restrict__ Sout,
          const uint32_t* __restrict__ wb, const uint32_t* __restrict__ nmask) {
    extern __shared__ uint32_t sm[];
    uint32_t* lut = sm;                       // [c][e][lane]
    uint32_t* wbs = sm + LUT_WORDS;           // [JCTA][8]

    const int tid  = threadIdx.x;
    const int wid  = tid >> 5;
    const int lane = tid & 31;
    const int bwb  = blockIdx.x * BWSET;
    const int jb   = blockIdx.y * JCTA;

    // stage this CTA's W-bit words (coalesced)
    for (int i = tid; i < JCTA * 8; i += RK_THREADS)
        wbs[i] = wb[jb * 8 + i];

    // build LUT: warp w owns chunks w*4 .. w*4+3 (Gray-code incremental)
    #pragma unroll
    for (int cc = 0; cc < 4; ++cc) {
        int c = wid * 4 + cc;
        const uint32_t* sp = Sin + (size_t)(c * 4) * NBW + bwb + lane;
        uint32_t s0 = sp[0], s1 = sp[NBW], s2 = sp[2 * NBW], s3 = sp[3 * NBW];
        uint32_t* L = lut + c * (16 * 32) + lane;
        uint32_t t = 0;
        L[0 * 32] = t;
        t ^= s0; L[1 * 32] = t;   t ^= s1; L[3 * 32] = t;
        t ^= s0; L[2 * 32] = t;   t ^= s2; L[6 * 32] = t;
        t ^= s0; L[7 * 32] = t;   t ^= s1; L[5 * 32] = t;
        t ^= s0; L[4 * 32] = t;   t ^= s3; L[12 * 32] = t;
        t ^= s0; L[13 * 32] = t;  t ^= s1; L[15 * 32] = t;
        t ^= s0; L[14 * 32] = t;  t ^= s2; L[10 * 32] = t;
        t ^= s0; L[11 * 32] = t;  t ^= s1; L[9 * 32] = t;
        t ^= s0; L[8 * 32] = t;
    }
    __syncthreads();

    // each warp computes 8 output words (j columns) for its 32 bw lanes
    #pragma unroll 1
    for (int jj = 0; jj < 8; ++jj) {
        int jl = wid * 8 + jj;                // local j
        int j  = jb + jl;
        const uint32_t* wd = wbs + jl * 8;
        uint32_t acc0 = 0, acc1 = 0;          // two chains for ILP
        #pragma unroll
        for (int cw = 0; cw < 8; ++cw) {
            uint32_t wword = wd[cw];          // uniform LDS
            #pragma unroll
            for (int n = 0; n < 8; n += 2) {
                int c0 = cw * 8 + n, c1 = c0 + 1;
                uint32_t i0 = (wword >> (n * 4)) & 15u;
                uint32_t i1 = (wword >> (n * 4 + 4)) & 15u;
                acc0 ^= lut[(c0 * 16 + i0) * 32 + lane];
                acc1 ^= lut[(c1 * 16 + i1) * 32 + lane];
            }
        }
        uint32_t r = acc0 ^ acc1 ^ nmask[j];
        Sout[(size_t)j * NBW + bwb + lane] = r;
    }
}

// ---------------- unpack final bits to fp32 ----------------
__global__ void unpack_state(const uint32_t* __restrict__ S, float* __restrict__ out) {
    __shared__ uint32_t smw[HID];
    int bw = blockIdx.x;
    int tid = threadIdx.x;                    // 256 threads
    smw[tid] = S[(size_t)tid * NBW + bw];     // k = tid
    __syncthreads();
    int b  = tid >> 3;                        // row within group (0..31)
    int kq = (tid & 7) * 32;                  // 32 k per thread
    float* dst = out + ((size_t)bw * 32 + b) * HID + kq;
    #pragma unroll
    for (int q = 0; q < 8; ++q) {
        float4 v;
        v.x = (float)((smw[kq + q * 4 + 0] >> b) & 1u);
        v.y = (float)((smw[kq + q * 4 + 1] >> b) & 1u);
        v.z = (float)((smw[kq + q * 4 + 2] >> b) & 1u);
        v.w = (float)((smw[kq + q * 4 + 3] >> b) & 1u);
        reinterpret_cast<float4*>(dst)[q] = v;
    }
}

// ---------------- launch ----------------
extern "C" void kernel_launch(void* const* d_in, const int* in_sizes, int n_in,
                              void* d_out, int out_size) {
    const float* state    = (const float*)d_in[0];   // [65536, 256]
    const float* matrices = (const float*)d_in[1];   // [64, 256, 256]
    const float* noise    = (const float*)d_in[2];   // [64, 256]
    float* out = (float*)d_out;

    pack_W<<<(ROUNDS * HID * 8 + 255) / 256, 256>>>(matrices);
    pack_noise<<<(ROUNDS * HID + 255) / 256, 256>>>(noise);
    pack_state<<<(NBW * 32 + 255) / 256, 256>>>(state);

    static uint32_t* S0 = nullptr;
    uint32_t *s0, *s1;
    cudaGetSymbolAddress((void**)&s0, g_S);          // not an allocation
    s1 = s0 + (size_t)HID * NBW;
    uint32_t* wbp;
    cudaGetSymbolAddress((void**)&wbp, g_Wb);
    uint32_t* nmp;
    cudaGetSymbolAddress((void**)&nmp, g_nm);
    (void)S0;

    cudaFuncSetAttribute(round_gf2, cudaFuncAttributeMaxDynamicSharedMemorySize, RK_SMEM);

    dim3 grid(NBW / BWSET, JSPLIT);
    for (int r = 0; r < ROUNDS; ++r) {
        const uint32_t* in  = (r & 1) ? s1 : s0;
        uint32_t*       dst = (r & 1) ? s0 : s1;
        round_gf2<<<grid, RK_THREADS, RK_SMEM>>>(in, dst, wbp + (size_t)r * HID * 8,
                                                 nmp + (size_t)r * HID);
    }
    // after 64 rounds result is back in s0
    unpack_state<<<NBW, HID>>>(s0, out);
}

// round 6
// speedup vs baseline: 8.0715x; 1.0145x over previous
#include <cuda_runtime.h>
#include <cuda_bf16.h>
#include <cstdint>

#define ROUNDS 64
#define HID 256
#define BATCH 65536
#define NBW (BATCH / 32)            // 2048 packed batch words
#define BWSET 32                    // bw words per CTA (one per lane)
#define JSPLIT 2
#define JCTA (HID / JSPLIT)         // 128 j per CTA
#define RK_THREADS 512              // 16 warps

// ---------------- device-global scratch (no allocs allowed) ----------------
__device__ uint32_t g_S[2][HID * NBW];          // bit-sliced state [k][bw], ping-pong (2x2MB)
__device__ uint32_t g_Wb[ROUNDS * HID * 8];     // W bits: [r][j][8 words over k]
__device__ uint32_t g_nm[ROUNDS * HID];         // noise masks: 0 or 0xFFFFFFFF

// ---------------- prep: pack |W| bits ----------------
__global__ void pack_W(const float* __restrict__ W) {
    int w = blockIdx.x * blockDim.x + threadIdx.x;      // word index
    if (w >= ROUNDS * HID * 8) return;
    const float* src = W + (size_t)w * 32;              // 32 consecutive k of row (r,j)
    uint32_t bits = 0;
    #pragma unroll
    for (int q = 0; q < 8; ++q) {
        float4 v = reinterpret_cast<const float4*>(src)[q];
        bits |= (v.x != 0.f ? 1u : 0u) << (q * 4 + 0);
        bits |= (v.y != 0.f ? 1u : 0u) << (q * 4 + 1);
        bits |= (v.z != 0.f ? 1u : 0u) << (q * 4 + 2);
        bits |= (v.w != 0.f ? 1u : 0u) << (q * 4 + 3);
    }
    g_Wb[w] = bits;
}

// ---------------- prep: noise -> full masks ----------------
__global__ void pack_noise(const float* __restrict__ noise) {
    int i = blockIdx.x * blockDim.x + threadIdx.x;
    if (i < ROUNDS * HID) g_nm[i] = (noise[i] != 0.f) ? 0xFFFFFFFFu : 0u;
}

// ---------------- prep: bit-slice the state ----------------
// S[k][bw]: bit b = state[bw*32+b][k]
__global__ void pack_state(const float* __restrict__ state) {
    int warp = (blockIdx.x * blockDim.x + threadIdx.x) >> 5;  // one warp per bw
    int lane = threadIdx.x & 31;
    if (warp >= NBW) return;
    const float* base = state + (size_t)warp * 32 * HID;
    #pragma unroll
    for (int kc = 0; kc < 8; ++kc) {
        int k = kc * 32 + lane;
        uint32_t word = 0;
        #pragma unroll
        for (int b = 0; b < 32; ++b)
            word |= (base[(size_t)b * HID + k] != 0.f ? 1u : 0u) << b;
        g_S[0][(size_t)k * NBW + warp] = word;
    }
}

// ---------------- per-round GF(2) kernel ----------------
// grid (64, 2): x = bw-set (32 words), y = j-half (128 j)
// SMEM: LUT[64 chunks][16 entries][32 lanes] (128KB) + wb slice (4KB)
#define LUT_WORDS (64 * 16 * 32)
#define RK_SMEM (LUT_WORDS * 4 + JCTA * 8 * 4)

__global__ void __launch_bounds__(RK_THREADS, 1)
round_gf2(const uint32_t* __restrict__ Sin, uint32_t* __restrict__ Sout,
          const uint32_t* __restrict__ wb, const uint32_t* __restrict__ nmask) {
    extern __shared__ uint32_t sm[];
    uint32_t* lut = sm;                       // [c][e][lane]
    uint32_t* wbs = sm + LUT_WORDS;           // [JCTA][8]

    const int tid  = threadIdx.x;
    const int wid  = tid >> 5;
    const int lane = tid & 31;
    const int bwb  = blockIdx.x * BWSET;
    const int jb   = blockIdx.y * JCTA;

    // stage this CTA's W-bit words (coalesced)
    for (int i = tid; i < JCTA * 8; i += RK_THREADS)
        wbs[i] = wb[jb * 8 + i];

    // build LUT: warp w owns chunks w*4 .. w*4+3 (Gray-code incremental)
    #pragma unroll
    for (int cc = 0; cc < 4; ++cc) {
        int c = wid * 4 + cc;
        const uint32_t* sp = Sin + (size_t)(c * 4) * NBW + bwb + lane;
        uint32_t s0 = sp[0], s1 = sp[NBW], s2 = sp[2 * NBW], s3 = sp[3 * NBW];
        uint32_t* L = lut + c * (16 * 32) + lane;
        uint32_t t = 0;
        L[0 * 32] = t;
        t ^= s0; L[1 * 32] = t;   t ^= s1; L[3 * 32] = t;
        t ^= s0; L[2 * 32] = t;   t ^= s2; L[6 * 32] = t;
        t ^= s0; L[7 * 32] = t;   t ^= s1; L[5 * 32] = t;
        t ^= s0; L[4 * 32] = t;   t ^= s3; L[12 * 32] = t;
        t ^= s0; L[13 * 32] = t;  t ^= s1; L[15 * 32] = t;
        t ^= s0; L[14 * 32] = t;  t ^= s2; L[10 * 32] = t;
        t ^= s0; L[11 * 32] = t;  t ^= s1; L[9 * 32] = t;
        t ^= s0; L[8 * 32] = t;
    }
    __syncthreads();

    // each warp computes 8 output words (j columns) for its 32 bw lanes
    #pragma unroll 1
    for (int jj = 0; jj < 8; ++jj) {
        int jl = wid * 8 + jj;                // local j
        int j  = jb + jl;
        const uint32_t* wd = wbs + jl * 8;
        uint32_t acc0 = 0, acc1 = 0;          // two chains for ILP
        #pragma unroll
        for (int cw = 0; cw < 8; ++cw) {
            uint32_t wword = wd[cw];          // uniform LDS
            #pragma unroll
            for (int n = 0; n < 8; n += 2) {
                int c0 = cw * 8 + n, c1 = c0 + 1;
                uint32_t i0 = (wword >> (n * 4)) & 15u;
                uint32_t i1 = (wword >> (n * 4 + 4)) & 15u;
                acc0 ^= lut[(c0 * 16 + i0) * 32 + lane];
                acc1 ^= lut[(c1 * 16 + i1) * 32 + lane];
            }
        }
        uint32_t r = acc0 ^ acc1 ^ nmask[j];
        Sout[(size_t)j * NBW + bwb + lane] = r;
    }
}

// ---------------- unpack final bits to fp32 ----------------
__global__ void unpack_state(const uint32_t* __restrict__ S, float* __restrict__ out) {
    __shared__ uint32_t smw[HID];
    int bw = blockIdx.x;
    int tid = threadIdx.x;                    // 256 threads
    smw[tid] = S[(size_t)tid * NBW + bw];     // k = tid
    __syncthreads();
    int b  = tid >> 3;                        // row within group (0..31)
    int kq = (tid & 7) * 32;                  // 32 k per thread
    float* dst = out + ((size_t)bw * 32 + b) * HID + kq;
    #pragma unroll
    for (int q = 0; q < 8; ++q) {
        float4 v;
        v.x = (float)((smw[kq + q * 4 + 0] >> b) & 1u);
        v.y = (float)((smw[kq + q * 4 + 1] >> b) & 1u);
        v.z = (float)((smw[kq + q * 4 + 2] >> b) & 1u);
        v.w = (float)((smw[kq + q * 4 + 3] >> b) & 1u);
        reinterpret_cast<float4*>(dst)[q] = v;
    }
}

// ---------------- launch ----------------
extern "C" void kernel_launch(void* const* d_in, const int* in_sizes, int n_in,
                              void* d_out, int out_size) {
    const float* state    = (const float*)d_in[0];   // [65536, 256]
    const float* matrices = (const float*)d_in[1];   // [64, 256, 256]
    const float* noise    = (const float*)d_in[2];   // [64, 256]
    float* out = (float*)d_out;

    pack_W<<<(ROUNDS * HID * 8 + 255) / 256, 256>>>(matrices);
    pack_noise<<<(ROUNDS * HID + 255) / 256, 256>>>(noise);
    pack_state<<<(NBW * 32 + 255) / 256, 256>>>(state);

    static uint32_t* S0 = nullptr;
    uint32_t *s0, *s1;
    cudaGetSymbolAddress((void**)&s0, g_S);          // not an allocation
    s1 = s0 + (size_t)HID * NBW;
    uint32_t* wbp;
    cudaGetSymbolAddress((void**)&wbp, g_Wb);
    uint32_t* nmp;
    cudaGetSymbolAddress((void**)&nmp, g_nm);
    (void)S0;

    cudaFuncSetAttribute(round_gf2, cudaFuncAttributeMaxDynamicSharedMemorySize, RK_SMEM);

    dim3 grid(NBW / BWSET, JSPLIT);
    for (int r = 0; r < ROUNDS; ++r) {
        const uint32_t* in  = (r & 1) ? s1 : s0;
        uint32_t*       dst = (r & 1) ? s0 : s1;
        round_gf2<<<grid, RK_THREADS, RK_SMEM>>>(in, dst, wbp + (size_t)r * HID * 8,
                                                 nmp + (size_t)r * HID);
    }
    // after 64 rounds result is back in s0
    unpack_state<<<NBW, HID>>>(s0, out);
}

// round 7
// speedup vs baseline: 8.0720x; 1.0001x over previous
#include <cuda_runtime.h>
#include <cuda_bf16.h>
#include <cstdint>

#define ROUNDS 64
#define HID 256
#define BATCH 65536
#define NBW (BATCH / 32)            // 2048 packed batch words
#define BWSET 32                    // bw words per CTA (one per lane)
#define JSPLIT 2
#define JCTA (HID / JSPLIT)         // 128 j per CTA
#define RK_THREADS 512              // 16 warps

// ---------------- device-global scratch (no allocs allowed) ----------------
__device__ uint32_t g_S[2][HID * NBW];          // bit-sliced state [k][bw], ping-pong (2x2MB)
__device__ uint32_t g_Wb[ROUNDS * HID * 8];     // W bits: [r][j][8 words over k]
__device__ uint32_t g_nm[ROUNDS * HID];         // noise masks: 0 or 0xFFFFFFFF

// ---------------- prep: pack |W| bits ----------------
__global__ void pack_W(const float* __restrict__ W) {
    int w = blockIdx.x * blockDim.x + threadIdx.x;      // word index
    if (w >= ROUNDS * HID * 8) return;
    const float* src = W + (size_t)w * 32;              // 32 consecutive k of row (r,j)
    uint32_t bits = 0;
    #pragma unroll
    for (int q = 0; q < 8; ++q) {
        float4 v = reinterpret_cast<const float4*>(src)[q];
        bits |= (v.x != 0.f ? 1u : 0u) << (q * 4 + 0);
        bits |= (v.y != 0.f ? 1u : 0u) << (q * 4 + 1);
        bits |= (v.z != 0.f ? 1u : 0u) << (q * 4 + 2);
        bits |= (v.w != 0.f ? 1u : 0u) << (q * 4 + 3);
    }
    g_Wb[w] = bits;
}

// ---------------- prep: noise -> full masks ----------------
__global__ void pack_noise(const float* __restrict__ noise) {
    int i = blockIdx.x * blockDim.x + threadIdx.x;
    if (i < ROUNDS * HID) g_nm[i] = (noise[i] != 0.f) ? 0xFFFFFFFFu : 0u;
}

// ---------------- prep: bit-slice the state ----------------
// S[k][bw]: bit b = state[bw*32+b][k]
__global__ void pack_state(const float* __restrict__ state) {
    int warp = (blockIdx.x * blockDim.x + threadIdx.x) >> 5;  // one warp per bw
    int lane = threadIdx.x & 31;
    if (warp >= NBW) return;
    const float* base = state + (size_t)warp * 32 * HID;
    #pragma unroll
    for (int kc = 0; kc < 8; ++kc) {
        int k = kc * 32 + lane;
        uint32_t word = 0;
        #pragma unroll
        for (int b = 0; b < 32; ++b)
            word |= (base[(size_t)b * HID + k] != 0.f ? 1u : 0u) << b;
        g_S[0][(size_t)k * NBW + warp] = word;
    }
}

// ---------------- per-round GF(2) kernel ----------------
// grid (64, 2): x = bw-set (32 words), y = j-half (128 j)
// SMEM: LUT[64 chunks][16 entries][32 lanes] (128KB) + wb slice (4KB)
#define LUT_WORDS (64 * 16 * 32)
#define RK_SMEM (LUT_WORDS * 4 + JCTA * 8 * 4)

__global__ void __launch_bounds__(RK_THREADS, 1)
round_gf2(const uint32_t* __restrict__ Sin, uint32_t* __restrict__ Sout,
          const uint32_t* __restrict__ wb, const uint32_t* __restrict__ nmask) {
    extern __shared__ uint32_t sm[];
    uint32_t* lut = sm;                       // [c][e][lane]
    uint32_t* wbs = sm + LUT_WORDS;           // [JCTA][8]

    const int tid  = threadIdx.x;
    const int wid  = tid >> 5;
    const int lane = tid & 31;
    const int bwb  = blockIdx.x * BWSET;
    const int jb   = blockIdx.y * JCTA;

    // stage this CTA's W-bit words (coalesced)
    for (int i = tid; i < JCTA * 8; i += RK_THREADS)
        wbs[i] = wb[jb * 8 + i];

    // build LUT: warp w owns chunks w*4 .. w*4+3 (Gray-code incremental)
    #pragma unroll
    for (int cc = 0; cc < 4; ++cc) {
        int c = wid * 4 + cc;
        const uint32_t* sp = Sin + (size_t)(c * 4) * NBW + bwb + lane;
        uint32_t s0 = sp[0], s1 = sp[NBW], s2 = sp[2 * NBW], s3 = sp[3 * NBW];
        uint32_t* L = lut + c * (16 * 32) + lane;
        uint32_t t = 0;
        L[0 * 32] = t;
        t ^= s0; L[1 * 32] = t;   t ^= s1; L[3 * 32] = t;
        t ^= s0; L[2 * 32] = t;   t ^= s2; L[6 * 32] = t;
        t ^= s0; L[7 * 32] = t;   t ^= s1; L[5 * 32] = t;
        t ^= s0; L[4 * 32] = t;   t ^= s3; L[12 * 32] = t;
        t ^= s0; L[13 * 32] = t;  t ^= s1; L[15 * 32] = t;
        t ^= s0; L[14 * 32] = t;  t ^= s2; L[10 * 32] = t;
        t ^= s0; L[11 * 32] = t;  t ^= s1; L[9 * 32] = t;
        t ^= s0; L[8 * 32] = t;
    }
    __syncthreads();

    // each warp computes 8 output words (j columns) for its 32 bw lanes
    #pragma unroll 1
    for (int jj = 0; jj < 8; ++jj) {
        int jl = wid * 8 + jj;                // local j
        int j  = jb + jl;
        const uint32_t* wd = wbs + jl * 8;
        uint32_t acc0 = 0, acc1 = 0;          // two chains for ILP
        #pragma unroll
        for (int cw = 0; cw < 8; ++cw) {
            uint32_t wword = wd[cw];          // uniform LDS
            #pragma unroll
            for (int n = 0; n < 8; n += 2) {
                int c0 = cw * 8 + n, c1 = c0 + 1;
                uint32_t i0 = (wword >> (n * 4)) & 15u;
                uint32_t i1 = (wword >> (n * 4 + 4)) & 15u;
                acc0 ^= lut[(c0 * 16 + i0) * 32 + lane];
                acc1 ^= lut[(c1 * 16 + i1) * 32 + lane];
            }
        }
        uint32_t r = acc0 ^ acc1 ^ nmask[j];
        Sout[(size_t)j * NBW + bwb + lane] = r;
    }
}

// ---------------- unpack final bits to fp32 ----------------
__global__ void unpack_state(const uint32_t* __restrict__ S, float* __restrict__ out) {
    __shared__ uint32_t smw[HID];
    int bw = blockIdx.x;
    int tid = threadIdx.x;                    // 256 threads
    smw[tid] = S[(size_t)tid * NBW + bw];     // k = tid
    __syncthreads();
    int b  = tid >> 3;                        // row within group (0..31)
    int kq = (tid & 7) * 32;                  // 32 k per thread
    float* dst = out + ((size_t)bw * 32 + b) * HID + kq;
    #pragma unroll
    for (int q = 0; q < 8; ++q) {
        float4 v;
        v.x = (float)((smw[kq + q * 4 + 0] >> b) & 1u);
        v.y = (float)((smw[kq + q * 4 + 1] >> b) & 1u);
        v.z = (float)((smw[kq + q * 4 + 2] >> b) & 1u);
        v.w = (float)((smw[kq + q * 4 + 3] >> b) & 1u);
        reinterpret_cast<float4*>(dst)[q] = v;
    }
}

// ---------------- launch ----------------
extern "C" void kernel_launch(void* const* d_in, const int* in_sizes, int n_in,
                              void* d_out, int out_size) {
    const float* state    = (const float*)d_in[0];   // [65536, 256]
    const float* matrices = (const float*)d_in[1];   // [64, 256, 256]
    const float* noise    = (const float*)d_in[2];   // [64, 256]
    float* out = (float*)d_out;

    pack_W<<<(ROUNDS * HID * 8 + 255) / 256, 256>>>(matrices);
    pack_noise<<<(ROUNDS * HID + 255) / 256, 256>>>(noise);
    pack_state<<<(NBW * 32 + 255) / 256, 256>>>(state);

    static uint32_t* S0 = nullptr;
    uint32_t *s0, *s1;
    cudaGetSymbolAddress((void**)&s0, g_S);          // not an allocation
    s1 = s0 + (size_t)HID * NBW;
    uint32_t* wbp;
    cudaGetSymbolAddress((void**)&wbp, g_Wb);
    uint32_t* nmp;
    cudaGetSymbolAddress((void**)&nmp, g_nm);
    (void)S0;

    cudaFuncSetAttribute(round_gf2, cudaFuncAttributeMaxDynamicSharedMemorySize, RK_SMEM);

    dim3 grid(NBW / BWSET, JSPLIT);
    for (int r = 0; r < ROUNDS; ++r) {
        const uint32_t* in  = (r & 1) ? s1 : s0;
        uint32_t*       dst = (r & 1) ? s0 : s1;
        round_gf2<<<grid, RK_THREADS, RK_SMEM>>>(in, dst, wbp + (size_t)r * HID * 8,
                                                 nmp + (size_t)r * HID);
    }
    // after 64 rounds result is back in s0
    unpack_state<<<NBW, HID>>>(s0, out);
}